// round 5
// baseline (speedup 1.0000x reference)
#include <cuda_runtime.h>
#include <cuda_bf16.h>
#include <math.h>
#include <stdint.h>

// Problem constants
#define B_ 8
#define C_ 512
#define N_ 2048
#define P_ 256

// ---------------- scratch (static device globals; no allocation) ----------------
__device__ __nv_bfloat16 d_xsA[(size_t)B_ * N_ * 3 * C_];   // x^T split, A-pattern [b][n][3C]
__device__ __nv_bfloat16 d_xsB[(size_t)B_ * N_ * 3 * C_];   // x^T split, B-pattern
__device__ __nv_bfloat16 d_WthS[P_ * 3 * C_];               // B-pattern
__device__ __nv_bfloat16 d_WphS[P_ * 3 * C_];               // B-pattern
__device__ __nv_bfloat16 d_WgS [P_ * 3 * C_];               // A-pattern
__device__ __nv_bfloat16 d_WzS [C_ * 3 * P_];               // A-pattern
__device__ __nv_bfloat16 d_thS[(size_t)B_ * N_ * 3 * P_];   // theta split A-pattern
__device__ __nv_bfloat16 d_phS[(size_t)B_ * N_ * 3 * P_];   // phi split B-pattern
__device__ __nv_bfloat16 d_gS [(size_t)B_ * P_ * 3 * N_];   // g^T split B-pattern [b][p][3N]
__device__ float         d_Sf [(size_t)B_ * N_ * N_];       // scores fp32
__device__ __nv_bfloat16 d_SsP[(size_t)B_ * N_ * 3 * N_];   // softmax probs split A-pattern
__device__ __nv_bfloat16 d_OS [(size_t)B_ * N_ * 3 * P_];   // attention out split B-pattern
__device__ float d_zp[(size_t)C_ * B_ * N_];                // z channel-major [C][B*N]
__device__ float d_scale[C_];
__device__ float d_shift[C_];

// ---------------- helpers ----------------
__device__ __forceinline__ uint32_t smem_to_u32(const void* p) {
    uint32_t a;
    asm("{ .reg .u64 t; cvta.to.shared.u64 t, %1; cvt.u32.u64 %0, t; }" : "=r"(a) : "l"(p));
    return a;
}
__device__ __forceinline__ void split2(float v, __nv_bfloat16& h, __nv_bfloat16& l) {
    h = __float2bfloat16(v);
    l = __float2bfloat16(v - __bfloat162float(h));
}

// ---------------- combined weight split (one launch) ----------------
// y selects: 0=Wth(B-pat,K=C) 1=Wph(B-pat,K=C) 2=Wg(A-pat,K=C) 3=Wz(A-pat,K=P)
__global__ void split_all_kernel(const float* __restrict__ Wth, const float* __restrict__ Wph,
                                 const float* __restrict__ Wg,  const float* __restrict__ Wz,
                                 __nv_bfloat16* __restrict__ WthS, __nv_bfloat16* __restrict__ WphS,
                                 __nv_bfloat16* __restrict__ WgS,  __nv_bfloat16* __restrict__ WzS)
{
    const int which = blockIdx.y;
    const int idx = blockIdx.x * blockDim.x + threadIdx.x;   // 0..P*C-1 (all 4 are P*C elems)
    if (idx >= P_ * C_) return;
    const float* in;
    __nv_bfloat16* out;
    int K, patA;
    if      (which == 0) { in = Wth; out = WthS; K = C_; patA = 0; }
    else if (which == 1) { in = Wph; out = WphS; K = C_; patA = 0; }
    else if (which == 2) { in = Wg;  out = WgS;  K = C_; patA = 1; }
    else                 { in = Wz;  out = WzS;  K = P_; patA = 1; }
    int r = idx / K, k = idx % K;
    __nv_bfloat16 h, l;
    split2(in[idx], h, l);
    __nv_bfloat16* o = out + (size_t)r * (3 * K);
    o[k] = h;
    if (patA) { o[K + k] = h; o[2 * K + k] = l; }
    else      { o[K + k] = l; o[2 * K + k] = h; }
}

// ---------------- x transpose + split ----------------
__global__ void xsplit_kernel(const float* __restrict__ x,
                              __nv_bfloat16* __restrict__ xsA,
                              __nv_bfloat16* __restrict__ xsB)
{
    __shared__ float t[32][33];
    const int b = blockIdx.z;
    const int n0 = blockIdx.x * 32, c0 = blockIdx.y * 32;
    const int tx = threadIdx.x, ty = threadIdx.y;
    const float* xb = x + (size_t)b * C_ * N_;
    t[ty][tx] = xb[(size_t)(c0 + ty) * N_ + n0 + tx];
    __syncthreads();
    float v = t[tx][ty];
    int n = n0 + ty, c = c0 + tx;
    __nv_bfloat16 h, l;
    split2(v, h, l);
    size_t row = ((size_t)b * N_ + n) * (size_t)(3 * C_);
    xsA[row + c] = h; xsA[row + C_ + c] = h; xsA[row + 2 * C_ + c] = l;
    xsB[row + c] = h; xsB[row + C_ + c] = l; xsB[row + 2 * C_ + c] = h;
}

// ---------------- mma.sync bf16 GEMM: C[i,j] = sum_k A[i,k]*B[j,k] ----------------
// Tile: 128x128, 8 warps (warp grid 4x2 -> warp tile 32x64), k-chunk 64, 3-stage cp.async.
// mode 0: fp32 out; mode 1: split A-pattern (hi@0,hi@J,lo@2J); mode 2: split B-pattern.
#define CH 64
#define PAD 72
#define STG_ELEMS (128 * PAD)              // per operand per stage (bf16 elems)
#define GEMM_SMEM (6 * STG_ELEMS * 2)      // 3 stages x (A+B)

__global__ void __launch_bounds__(256, 2) gemm_mma_kernel(
    const __nv_bfloat16* __restrict__ A, int lda,
    const __nv_bfloat16* __restrict__ Bp, int ldb,
    void* __restrict__ Cout, int ldc, int Kp, int mode, int J,
    size_t sA, size_t sB, size_t sC)
{
    extern __shared__ __nv_bfloat16 sm[];
    // layout: [A0][B0][A1][B1][A2][B2]
    const uint32_t smu = smem_to_u32(sm);

    const int tid  = threadIdx.x;
    const int wid  = tid >> 5;
    const int lane = tid & 31;
    const int wm = wid & 3;        // warp m-block (32 rows)
    const int wn = wid >> 2;       // warp n-block (64 cols)
    const int bz = blockIdx.z;
    A  += (size_t)bz * sA;
    Bp += (size_t)bz * sB;
    const int m0 = blockIdx.y * 128;
    const int j0 = blockIdx.x * 128;

    float acc[2][8][4];
#pragma unroll
    for (int mt = 0; mt < 2; mt++)
#pragma unroll
        for (int nb = 0; nb < 8; nb++)
#pragma unroll
            for (int q = 0; q < 4; q++) acc[mt][nb][q] = 0.f;

    auto issue_chunk = [&](int c, int buf) {
        const int k0 = c * CH;
        const uint32_t aBase = smu + (uint32_t)(2 * buf) * STG_ELEMS * 2;
        const uint32_t bBase = smu + (uint32_t)(2 * buf + 1) * STG_ELEMS * 2;
#pragma unroll
        for (int i = 0; i < 4; i++) {
            int lin = tid + i * 256;          // 0..1023
            int r  = lin >> 3;                // 0..127
            int c8 = lin & 7;                 // 0..7 (16B unit)
            const __nv_bfloat16* gA = A  + (size_t)(m0 + r) * lda + k0 + c8 * 8;
            const __nv_bfloat16* gB = Bp + (size_t)(j0 + r) * ldb + k0 + c8 * 8;
            uint32_t sa = aBase + (uint32_t)(r * PAD + c8 * 8) * 2;
            uint32_t sb = bBase + (uint32_t)(r * PAD + c8 * 8) * 2;
            asm volatile("cp.async.cg.shared.global [%0], [%1], 16;" :: "r"(sa), "l"(gA));
            asm volatile("cp.async.cg.shared.global [%0], [%1], 16;" :: "r"(sb), "l"(gB));
        }
        asm volatile("cp.async.commit_group;" ::: "memory");
    };

    const int NC = Kp / CH;
    issue_chunk(0, 0);
    if (NC > 1) issue_chunk(1, 1);

    int buf = 0;
    for (int c = 0; c < NC; c++) {
        if (c + 2 < NC) {
            issue_chunk(c + 2, (buf + 2) % 3);
            asm volatile("cp.async.wait_group 2;" ::: "memory");
        } else if (c + 1 < NC) {
            asm volatile("cp.async.wait_group 1;" ::: "memory");
        } else {
            asm volatile("cp.async.wait_group 0;" ::: "memory");
        }
        __syncthreads();

        const uint32_t aBase = smu + (uint32_t)(2 * buf) * STG_ELEMS * 2;
        const uint32_t bBase = smu + (uint32_t)(2 * buf + 1) * STG_ELEMS * 2;
        const int lrow = lane & 15;
        const int kun  = lane >> 4;       // 0 or 1 -> k +0 / +8

#pragma unroll
        for (int ks = 0; ks < 4; ks++) {
            const int k0 = ks * 16;
            uint32_t af[2][4];
#pragma unroll
            for (int mt = 0; mt < 2; mt++) {
                uint32_t addr = aBase +
                    (uint32_t)((wm * 32 + mt * 16 + lrow) * PAD + k0 + kun * 8) * 2;
                asm volatile(
                    "ldmatrix.sync.aligned.m8n8.x4.shared.b16 {%0,%1,%2,%3}, [%4];"
                    : "=r"(af[mt][0]), "=r"(af[mt][1]), "=r"(af[mt][2]), "=r"(af[mt][3])
                    : "r"(addr));
            }
            uint32_t bfr[8][2];
#pragma unroll
            for (int nb2 = 0; nb2 < 4; nb2++) {
                uint32_t r0, r1, r2, r3;
                uint32_t addr = bBase +
                    (uint32_t)((wn * 64 + nb2 * 16 + lrow) * PAD + k0 + kun * 8) * 2;
                asm volatile(
                    "ldmatrix.sync.aligned.m8n8.x4.shared.b16 {%0,%1,%2,%3}, [%4];"
                    : "=r"(r0), "=r"(r1), "=r"(r2), "=r"(r3)
                    : "r"(addr));
                bfr[nb2 * 2][0] = r0; bfr[nb2 * 2][1] = r2;
                bfr[nb2 * 2 + 1][0] = r1; bfr[nb2 * 2 + 1][1] = r3;
            }
#pragma unroll
            for (int mt = 0; mt < 2; mt++)
#pragma unroll
                for (int nb = 0; nb < 8; nb++) {
                    asm volatile(
                        "mma.sync.aligned.m16n8k16.row.col.f32.bf16.bf16.f32 "
                        "{%0,%1,%2,%3}, {%4,%5,%6,%7}, {%8,%9}, {%0,%1,%2,%3};"
                        : "+f"(acc[mt][nb][0]), "+f"(acc[mt][nb][1]),
                          "+f"(acc[mt][nb][2]), "+f"(acc[mt][nb][3])
                        : "r"(af[mt][0]), "r"(af[mt][1]), "r"(af[mt][2]), "r"(af[mt][3]),
                          "r"(bfr[nb][0]), "r"(bfr[nb][1]));
                }
        }
        __syncthreads();
        buf = (buf + 1) % 3;
    }

    // ---------------- epilogue ----------------
    const int g = lane >> 2;
    const int t = lane & 3;
#pragma unroll
    for (int mt = 0; mt < 2; mt++) {
        const int row0 = m0 + wm * 32 + mt * 16 + g;
        const int row1 = row0 + 8;
#pragma unroll
        for (int nb = 0; nb < 8; nb++) {
            const int col = j0 + wn * 64 + nb * 8 + t * 2;
            float d0 = acc[mt][nb][0], d1 = acc[mt][nb][1];
            float d2 = acc[mt][nb][2], d3 = acc[mt][nb][3];
            if (mode == 0) {
                float* base = (float*)Cout + (size_t)bz * sC;
                *(float2*)(base + (size_t)row0 * ldc + col) = make_float2(d0, d1);
                *(float2*)(base + (size_t)row1 * ldc + col) = make_float2(d2, d3);
            } else {
                __nv_bfloat16* base = (__nv_bfloat16*)Cout + (size_t)bz * sC;
                const int oh2 = (mode == 1) ? J : 2 * J;
                const int olo = (mode == 1) ? 2 * J : J;
                __nv_bfloat16 h0, l0, h1, l1;
                split2(d0, h0, l0); split2(d1, h1, l1);
                uint32_t hp = (uint32_t)__bfloat16_as_ushort(h0) | ((uint32_t)__bfloat16_as_ushort(h1) << 16);
                uint32_t lp = (uint32_t)__bfloat16_as_ushort(l0) | ((uint32_t)__bfloat16_as_ushort(l1) << 16);
                __nv_bfloat16* r0p = base + (size_t)row0 * ldc + col;
                *(uint32_t*)(r0p)       = hp;
                *(uint32_t*)(r0p + oh2) = hp;
                *(uint32_t*)(r0p + olo) = lp;
                split2(d2, h0, l0); split2(d3, h1, l1);
                hp = (uint32_t)__bfloat16_as_ushort(h0) | ((uint32_t)__bfloat16_as_ushort(h1) << 16);
                lp = (uint32_t)__bfloat16_as_ushort(l0) | ((uint32_t)__bfloat16_as_ushort(l1) << 16);
                __nv_bfloat16* r1p = base + (size_t)row1 * ldc + col;
                *(uint32_t*)(r1p)       = hp;
                *(uint32_t*)(r1p + oh2) = hp;
                *(uint32_t*)(r1p + olo) = lp;
            }
        }
    }
}

// ---------------- softmax + split(A-pattern) over rows of N_=2048 ----------------
__global__ void softmax_split_kernel(const float* __restrict__ S,
                                     __nv_bfloat16* __restrict__ Ssp)
{
    __shared__ float red[256];
    const size_t rowi = blockIdx.x;
    const float* row = S + rowi * N_;
    __nv_bfloat16* orow = Ssp + rowi * (size_t)(3 * N_);
    const int tid = threadIdx.x;

    float4 v0 = ((const float4*)row)[tid];
    float4 v1 = ((const float4*)row)[tid + 256];

    float m = fmaxf(fmaxf(fmaxf(v0.x, v0.y), fmaxf(v0.z, v0.w)),
                    fmaxf(fmaxf(v1.x, v1.y), fmaxf(v1.z, v1.w)));
    red[tid] = m;
    __syncthreads();
    for (int s = 128; s > 0; s >>= 1) {
        if (tid < s) red[tid] = fmaxf(red[tid], red[tid + s]);
        __syncthreads();
    }
    const float rowmax = red[0];
    __syncthreads();

    v0.x = expf(v0.x - rowmax); v0.y = expf(v0.y - rowmax);
    v0.z = expf(v0.z - rowmax); v0.w = expf(v0.w - rowmax);
    v1.x = expf(v1.x - rowmax); v1.y = expf(v1.y - rowmax);
    v1.z = expf(v1.z - rowmax); v1.w = expf(v1.w - rowmax);

    float sum = (v0.x + v0.y + v0.z + v0.w) + (v1.x + v1.y + v1.z + v1.w);
    red[tid] = sum;
    __syncthreads();
    for (int s = 128; s > 0; s >>= 1) {
        if (tid < s) red[tid] += red[tid + s];
        __syncthreads();
    }
    const float inv = 1.0f / red[0];

    v0.x *= inv; v0.y *= inv; v0.z *= inv; v0.w *= inv;
    v1.x *= inv; v1.y *= inv; v1.z *= inv; v1.w *= inv;

    float vv[8] = {v0.x, v0.y, v0.z, v0.w, v1.x, v1.y, v1.z, v1.w};
    int pos[2] = {tid * 4, 1024 + tid * 4};
#pragma unroll
    for (int gsel = 0; gsel < 2; gsel++) {
        __nv_bfloat16 h[4], l[4];
#pragma unroll
        for (int q = 0; q < 4; q++) split2(vv[gsel * 4 + q], h[q], l[q]);
        uint32_t h01 = (uint32_t)__bfloat16_as_ushort(h[0]) | ((uint32_t)__bfloat16_as_ushort(h[1]) << 16);
        uint32_t h23 = (uint32_t)__bfloat16_as_ushort(h[2]) | ((uint32_t)__bfloat16_as_ushort(h[3]) << 16);
        uint32_t l01 = (uint32_t)__bfloat16_as_ushort(l[0]) | ((uint32_t)__bfloat16_as_ushort(l[1]) << 16);
        uint32_t l23 = (uint32_t)__bfloat16_as_ushort(l[2]) | ((uint32_t)__bfloat16_as_ushort(l[3]) << 16);
        int p = pos[gsel];
        *(uint2*)(orow + p)          = make_uint2(h01, h23);
        *(uint2*)(orow + N_ + p)     = make_uint2(h01, h23);
        *(uint2*)(orow + 2 * N_ + p) = make_uint2(l01, l23);
    }
}

// ---------------- BN batch statistics per channel ----------------
__global__ void bn_stats_kernel(const float* __restrict__ zp,
                                const float* __restrict__ gamma,
                                const float* __restrict__ beta,
                                float* __restrict__ scale,
                                float* __restrict__ shift)
{
    __shared__ double rs[256];
    __shared__ double rs2[256];
    const int c = blockIdx.x;
    const int tid = threadIdx.x;
    const float* row = zp + (size_t)c * (B_ * N_);

    double s = 0.0, s2 = 0.0;
    const int n4 = (B_ * N_) / 4;
    for (int i = tid; i < n4; i += 256) {
        float4 v = ((const float4*)row)[i];
        s  += (double)v.x + (double)v.y + (double)v.z + (double)v.w;
        s2 += (double)v.x * v.x + (double)v.y * v.y +
              (double)v.z * v.z + (double)v.w * v.w;
    }
    rs[tid] = s; rs2[tid] = s2;
    __syncthreads();
    for (int st = 128; st > 0; st >>= 1) {
        if (tid < st) { rs[tid] += rs[tid + st]; rs2[tid] += rs2[tid + st]; }
        __syncthreads();
    }
    if (tid == 0) {
        const double M = (double)(B_ * N_);
        double mean = rs[0] / M;
        double var  = rs2[0] / M - mean * mean;
        double inv  = 1.0 / sqrt(var + 1e-5);
        double sc   = (double)gamma[c] * inv;
        scale[c] = (float)sc;
        shift[c] = (float)((double)beta[c] - mean * sc);
    }
}

// ---------------- finalize ----------------
__global__ void finalize_kernel(const float* __restrict__ zp,
                                const float* __restrict__ x,
                                const float* __restrict__ scale,
                                const float* __restrict__ shift,
                                float* __restrict__ out)
{
    const size_t idx4 = (size_t)blockIdx.x * blockDim.x + threadIdx.x;
    const size_t total4 = (size_t)B_ * C_ * N_ / 4;
    if (idx4 >= total4) return;
    const int nq = N_ / 4;
    int n4 = (int)(idx4 % nq);
    int c  = (int)((idx4 / nq) % C_);
    int b  = (int)(idx4 / ((size_t)nq * C_));

    float4 z = ((const float4*)zp)[(size_t)c * (B_ * N_ / 4) + (size_t)b * nq + n4];
    float4 xv = ((const float4*)x)[idx4];
    const float sc = scale[c], sh = shift[c];
    float4 o;
    o.x = z.x * sc + sh + xv.x;
    o.y = z.y * sc + sh + xv.y;
    o.z = z.z * sc + sh + xv.z;
    o.w = z.w * sc + sh + xv.w;
    ((float4*)out)[idx4] = o;
}

// ---------------- launch ----------------
template <typename T>
static T* sym_addr(const void* sym)
{
    void* p = nullptr;
    cudaGetSymbolAddress(&p, sym);
    return (T*)p;
}

extern "C" void kernel_launch(void* const* d_in, const int* in_sizes, int n_in,
                              void* d_out, int out_size)
{
    const float* x     = (const float*)d_in[0];
    const float* Wg    = (const float*)d_in[1];
    const float* Wth   = (const float*)d_in[2];
    const float* Wph   = (const float*)d_in[3];
    const float* Wz    = (const float*)d_in[4];
    const float* gamma = (const float*)d_in[5];
    const float* beta  = (const float*)d_in[6];
    float* out = (float*)d_out;

    __nv_bfloat16* xsA  = sym_addr<__nv_bfloat16>(d_xsA);
    __nv_bfloat16* xsB  = sym_addr<__nv_bfloat16>(d_xsB);
    __nv_bfloat16* WthS = sym_addr<__nv_bfloat16>(d_WthS);
    __nv_bfloat16* WphS = sym_addr<__nv_bfloat16>(d_WphS);
    __nv_bfloat16* WgS  = sym_addr<__nv_bfloat16>(d_WgS);
    __nv_bfloat16* WzS  = sym_addr<__nv_bfloat16>(d_WzS);
    __nv_bfloat16* thS  = sym_addr<__nv_bfloat16>(d_thS);
    __nv_bfloat16* phS  = sym_addr<__nv_bfloat16>(d_phS);
    __nv_bfloat16* gS   = sym_addr<__nv_bfloat16>(d_gS);
    float*         Sf   = sym_addr<float>(d_Sf);
    __nv_bfloat16* SsP  = sym_addr<__nv_bfloat16>(d_SsP);
    __nv_bfloat16* OS   = sym_addr<__nv_bfloat16>(d_OS);
    float* zp    = sym_addr<float>(d_zp);
    float* scale = sym_addr<float>(d_scale);
    float* shift = sym_addr<float>(d_shift);

    cudaFuncSetAttribute(gemm_mma_kernel,
                         cudaFuncAttributeMaxDynamicSharedMemorySize, GEMM_SMEM);

    // 1) weight splits (single launch)
    split_all_kernel<<<dim3((P_ * C_ + 255) / 256, 4), 256>>>(
        Wth, Wph, Wg, Wz, WthS, WphS, WgS, WzS);
    // 2) x transpose + split
    xsplit_kernel<<<dim3(N_ / 32, C_ / 32, B_), dim3(32, 32)>>>(x, xsA, xsB);

    // 3) theta [b][n][3P] splitA
    gemm_mma_kernel<<<dim3(P_ / 128, N_ / 128, B_), 256, GEMM_SMEM>>>(
        xsA, 3 * C_, WthS, 3 * C_, thS, 3 * P_, 3 * C_, 1, P_,
        (size_t)N_ * 3 * C_, 0, (size_t)N_ * 3 * P_);
    // 4) phi [b][n][3P] splitB
    gemm_mma_kernel<<<dim3(P_ / 128, N_ / 128, B_), 256, GEMM_SMEM>>>(
        xsA, 3 * C_, WphS, 3 * C_, phS, 3 * P_, 3 * C_, 2, P_,
        (size_t)N_ * 3 * C_, 0, (size_t)N_ * 3 * P_);
    // 5) g^T [b][p][3N] splitB
    gemm_mma_kernel<<<dim3(N_ / 128, P_ / 128, B_), 256, GEMM_SMEM>>>(
        WgS, 3 * C_, xsB, 3 * C_, gS, 3 * N_, 3 * C_, 2, N_,
        0, (size_t)N_ * 3 * C_, (size_t)P_ * 3 * N_);
    // 6) scores fp32  <-- ncu -s 5 -c 1 captures this launch
    gemm_mma_kernel<<<dim3(N_ / 128, N_ / 128, B_), 256, GEMM_SMEM>>>(
        thS, 3 * P_, phS, 3 * P_, Sf, N_, 3 * P_, 0, 0,
        (size_t)N_ * 3 * P_, (size_t)N_ * 3 * P_, (size_t)N_ * N_);
    // 7) softmax + split
    softmax_split_kernel<<<B_ * N_, 256>>>(Sf, SsP);
    // 8) PV
    gemm_mma_kernel<<<dim3(P_ / 128, N_ / 128, B_), 256, GEMM_SMEM>>>(
        SsP, 3 * N_, gS, 3 * N_, OS, 3 * P_, 3 * N_, 2, P_,
        (size_t)N_ * 3 * N_, (size_t)P_ * 3 * N_, (size_t)N_ * 3 * P_);
    // 9) z fp32 [C][B*N]
    gemm_mma_kernel<<<dim3((B_ * N_) / 128, C_ / 128, 1), 256, GEMM_SMEM>>>(
        WzS, 3 * P_, OS, 3 * P_, zp, B_ * N_, 3 * P_, 0, 0, 0, 0, 0);

    // 10) BN + finalize
    bn_stats_kernel<<<C_, 256>>>(zp, gamma, beta, scale, shift);
    {
        const int total4 = B_ * C_ * N_ / 4;
        finalize_kernel<<<(total4 + 255) / 256, 256>>>(zp, x, scale, shift, out);
    }
}

// round 6
// speedup vs baseline: 1.0080x; 1.0080x over previous
#include <cuda_runtime.h>
#include <cuda_bf16.h>
#include <math.h>
#include <stdint.h>

// Problem constants
#define B_ 8
#define C_ 512
#define N_ 2048
#define P_ 256

// ---------------- scratch (static device globals; no allocation) ----------------
__device__ __nv_bfloat16 d_xsA[(size_t)B_ * N_ * 3 * C_];   // x^T split, A-pattern [b][n][3C]
__device__ __nv_bfloat16 d_xsB[(size_t)B_ * N_ * 3 * C_];   // x^T split, B-pattern
__device__ __nv_bfloat16 d_WthS[P_ * 3 * C_];               // B-pattern
__device__ __nv_bfloat16 d_WphS[P_ * 3 * C_];               // B-pattern
__device__ __nv_bfloat16 d_WgS [P_ * 3 * C_];               // A-pattern
__device__ __nv_bfloat16 d_WzS [C_ * 3 * P_];               // A-pattern
__device__ __nv_bfloat16 d_thS[(size_t)B_ * N_ * 3 * P_];   // theta split A-pattern
__device__ __nv_bfloat16 d_phS[(size_t)B_ * N_ * 3 * P_];   // phi split B-pattern
__device__ __nv_bfloat16 d_gS [(size_t)B_ * P_ * 3 * N_];   // g^T split B-pattern [b][p][3N]
__device__ float         d_Sf [(size_t)B_ * N_ * N_];       // scores fp32
__device__ __nv_bfloat16 d_SsP[(size_t)B_ * N_ * 3 * N_];   // softmax probs split A-pattern
__device__ __nv_bfloat16 d_OS [(size_t)B_ * N_ * 3 * P_];   // attention out split B-pattern
__device__ float d_zp[(size_t)C_ * B_ * N_];                // z channel-major [C][B*N]
__device__ float d_scale[C_];
__device__ float d_shift[C_];

// ---------------- helpers ----------------
__device__ __forceinline__ uint32_t smem_to_u32(const void* p) {
    uint32_t a;
    asm("{ .reg .u64 t; cvta.to.shared.u64 t, %1; cvt.u32.u64 %0, t; }" : "=r"(a) : "l"(p));
    return a;
}
__device__ __forceinline__ void split2(float v, __nv_bfloat16& h, __nv_bfloat16& l) {
    h = __float2bfloat16(v);
    l = __float2bfloat16(v - __bfloat162float(h));
}

// ---------------- combined weight split (one launch) ----------------
__global__ void split_all_kernel(const float* __restrict__ Wth, const float* __restrict__ Wph,
                                 const float* __restrict__ Wg,  const float* __restrict__ Wz,
                                 __nv_bfloat16* __restrict__ WthS, __nv_bfloat16* __restrict__ WphS,
                                 __nv_bfloat16* __restrict__ WgS,  __nv_bfloat16* __restrict__ WzS)
{
    const int which = blockIdx.y;
    const int idx = blockIdx.x * blockDim.x + threadIdx.x;
    if (idx >= P_ * C_) return;
    const float* in;
    __nv_bfloat16* out;
    int K, patA;
    if      (which == 0) { in = Wth; out = WthS; K = C_; patA = 0; }
    else if (which == 1) { in = Wph; out = WphS; K = C_; patA = 0; }
    else if (which == 2) { in = Wg;  out = WgS;  K = C_; patA = 1; }
    else                 { in = Wz;  out = WzS;  K = P_; patA = 1; }
    int r = idx / K, k = idx % K;
    __nv_bfloat16 h, l;
    split2(in[idx], h, l);
    __nv_bfloat16* o = out + (size_t)r * (3 * K);
    o[k] = h;
    if (patA) { o[K + k] = h; o[2 * K + k] = l; }
    else      { o[K + k] = l; o[2 * K + k] = h; }
}

// ---------------- x transpose + split ----------------
__global__ void xsplit_kernel(const float* __restrict__ x,
                              __nv_bfloat16* __restrict__ xsA,
                              __nv_bfloat16* __restrict__ xsB)
{
    __shared__ float t[32][33];
    const int b = blockIdx.z;
    const int n0 = blockIdx.x * 32, c0 = blockIdx.y * 32;
    const int tx = threadIdx.x, ty = threadIdx.y;
    const float* xb = x + (size_t)b * C_ * N_;
    t[ty][tx] = xb[(size_t)(c0 + ty) * N_ + n0 + tx];
    __syncthreads();
    float v = t[tx][ty];
    int n = n0 + ty, c = c0 + tx;
    __nv_bfloat16 h, l;
    split2(v, h, l);
    size_t row = ((size_t)b * N_ + n) * (size_t)(3 * C_);
    xsA[row + c] = h; xsA[row + C_ + c] = h; xsA[row + 2 * C_ + c] = l;
    xsB[row + c] = h; xsB[row + C_ + c] = l; xsB[row + 2 * C_ + c] = h;
}

// ---------------- mma.sync bf16 GEMM: C[i,j] = sum_k A[i,k]*B[j,k] ----------------
// Tile: 128x128, 8 warps (warp grid 4x2 -> warp tile 32x64), k-chunk 64, 3-stage cp.async.
// Mainloop: 1 barrier per chunk; B-group ping-pong; A-frag cross-ks prefetch.
#define CH 64
#define PAD 72
#define STG_ELEMS (128 * PAD)
#define GEMM_SMEM (6 * STG_ELEMS * 2)

#define LDSM4(d, addr) \
    asm volatile("ldmatrix.sync.aligned.m8n8.x4.shared.b16 {%0,%1,%2,%3}, [%4];" \
        : "=r"((d)[0]), "=r"((d)[1]), "=r"((d)[2]), "=r"((d)[3]) : "r"(addr))

#define MMA16816(ac, a, b0, b1) \
    asm volatile("mma.sync.aligned.m16n8k16.row.col.f32.bf16.bf16.f32 " \
        "{%0,%1,%2,%3}, {%4,%5,%6,%7}, {%8,%9}, {%0,%1,%2,%3};" \
        : "+f"((ac)[0]), "+f"((ac)[1]), "+f"((ac)[2]), "+f"((ac)[3]) \
        : "r"((a)[0]), "r"((a)[1]), "r"((a)[2]), "r"((a)[3]), "r"(b0), "r"(b1))

__global__ void __launch_bounds__(256, 2) gemm_mma_kernel(
    const __nv_bfloat16* __restrict__ A, int lda,
    const __nv_bfloat16* __restrict__ Bp, int ldb,
    void* __restrict__ Cout, int ldc, int Kp, int mode, int J,
    size_t sA, size_t sB, size_t sC)
{
    extern __shared__ __nv_bfloat16 sm[];
    const uint32_t smu = smem_to_u32(sm);

    const int tid  = threadIdx.x;
    const int wid  = tid >> 5;
    const int lane = tid & 31;
    const int wm = wid & 3;
    const int wn = wid >> 2;
    const int bz = blockIdx.z;
    A  += (size_t)bz * sA;
    Bp += (size_t)bz * sB;
    const int m0 = blockIdx.y * 128;
    const int j0 = blockIdx.x * 128;

    float acc[2][8][4];
#pragma unroll
    for (int mt = 0; mt < 2; mt++)
#pragma unroll
        for (int nb = 0; nb < 8; nb++)
#pragma unroll
            for (int q = 0; q < 4; q++) acc[mt][nb][q] = 0.f;

    auto issue_chunk = [&](int c, int buf) {
        const int k0 = c * CH;
        const uint32_t aBase = smu + (uint32_t)(2 * buf) * STG_ELEMS * 2;
        const uint32_t bBase = smu + (uint32_t)(2 * buf + 1) * STG_ELEMS * 2;
#pragma unroll
        for (int i = 0; i < 4; i++) {
            int lin = tid + i * 256;
            int r  = lin >> 3;
            int c8 = lin & 7;
            const __nv_bfloat16* gA = A  + (size_t)(m0 + r) * lda + k0 + c8 * 8;
            const __nv_bfloat16* gB = Bp + (size_t)(j0 + r) * ldb + k0 + c8 * 8;
            uint32_t sa = aBase + (uint32_t)(r * PAD + c8 * 8) * 2;
            uint32_t sb = bBase + (uint32_t)(r * PAD + c8 * 8) * 2;
            asm volatile("cp.async.cg.shared.global [%0], [%1], 16;" :: "r"(sa), "l"(gA));
            asm volatile("cp.async.cg.shared.global [%0], [%1], 16;" :: "r"(sb), "l"(gB));
        }
        asm volatile("cp.async.commit_group;" ::: "memory");
    };

    const int NC = Kp / CH;
    issue_chunk(0, 0);
    if (NC > 1) issue_chunk(1, 1);

    const int lrow = lane & 15;
    const int kun  = lane >> 4;
    const uint32_t aRowOff = (uint32_t)((wm * 32 + lrow) * PAD + kun * 8) * 2;
    const uint32_t bRowOff = (uint32_t)((wn * 64 + lrow) * PAD + kun * 8) * 2;

    int buf = 0;
    for (int c = 0; c < NC; c++) {
        if (c + 1 < NC) asm volatile("cp.async.wait_group 1;" ::: "memory");
        else            asm volatile("cp.async.wait_group 0;" ::: "memory");
        __syncthreads();
        if (c + 2 < NC) issue_chunk(c + 2, (buf + 2) % 3);

        const uint32_t aBase = smu + (uint32_t)(2 * buf) * STG_ELEMS * 2 + aRowOff;
        const uint32_t bBase = smu + (uint32_t)(2 * buf + 1) * STG_ELEMS * 2 + bRowOff;

        uint32_t af[2][2][4];   // [ks parity][mt][frag]
        uint32_t bg[2][4];      // B-group ping-pong

        // prefetch A fragments for ks=0
        LDSM4(af[0][0], aBase);
        LDSM4(af[0][1], aBase + 16 * PAD * 2);

#pragma unroll
        for (int ks = 0; ks < 4; ks++) {
            const int cur = ks & 1, nxt = cur ^ 1;
            const uint32_t kOff = (uint32_t)(ks * 32);          // 16 bf16 = 32 bytes
            // B group 0 for this ks
            LDSM4(bg[0], bBase + kOff);
#pragma unroll
            for (int nb2 = 0; nb2 < 4; nb2++) {
                const int gc = nb2 & 1, gn = gc ^ 1;
                if (nb2 < 3) {
                    LDSM4(bg[gn], bBase + kOff + (uint32_t)((nb2 + 1) * 16 * PAD * 2));
                } else if (ks < 3) {
                    LDSM4(af[nxt][0], aBase + kOff + 32);
                    LDSM4(af[nxt][1], aBase + kOff + 32 + 16 * PAD * 2);
                }
#pragma unroll
                for (int mt = 0; mt < 2; mt++) {
                    MMA16816(acc[mt][nb2 * 2],     af[cur][mt], bg[gc][0], bg[gc][2]);
                    MMA16816(acc[mt][nb2 * 2 + 1], af[cur][mt], bg[gc][1], bg[gc][3]);
                }
            }
        }
        buf = (buf + 1) % 3;
    }

    // ---------------- epilogue ----------------
    const int g = lane >> 2;
    const int t = lane & 3;
#pragma unroll
    for (int mt = 0; mt < 2; mt++) {
        const int row0 = m0 + wm * 32 + mt * 16 + g;
        const int row1 = row0 + 8;
#pragma unroll
        for (int nb = 0; nb < 8; nb++) {
            const int col = j0 + wn * 64 + nb * 8 + t * 2;
            float d0 = acc[mt][nb][0], d1 = acc[mt][nb][1];
            float d2 = acc[mt][nb][2], d3 = acc[mt][nb][3];
            if (mode == 0) {
                float* base = (float*)Cout + (size_t)bz * sC;
                *(float2*)(base + (size_t)row0 * ldc + col) = make_float2(d0, d1);
                *(float2*)(base + (size_t)row1 * ldc + col) = make_float2(d2, d3);
            } else {
                __nv_bfloat16* base = (__nv_bfloat16*)Cout + (size_t)bz * sC;
                const int oh2 = (mode == 1) ? J : 2 * J;
                const int olo = (mode == 1) ? 2 * J : J;
                __nv_bfloat16 h0, l0, h1, l1;
                split2(d0, h0, l0); split2(d1, h1, l1);
                uint32_t hp = (uint32_t)__bfloat16_as_ushort(h0) | ((uint32_t)__bfloat16_as_ushort(h1) << 16);
                uint32_t lp = (uint32_t)__bfloat16_as_ushort(l0) | ((uint32_t)__bfloat16_as_ushort(l1) << 16);
                __nv_bfloat16* r0p = base + (size_t)row0 * ldc + col;
                *(uint32_t*)(r0p)       = hp;
                *(uint32_t*)(r0p + oh2) = hp;
                *(uint32_t*)(r0p + olo) = lp;
                split2(d2, h0, l0); split2(d3, h1, l1);
                hp = (uint32_t)__bfloat16_as_ushort(h0) | ((uint32_t)__bfloat16_as_ushort(h1) << 16);
                lp = (uint32_t)__bfloat16_as_ushort(l0) | ((uint32_t)__bfloat16_as_ushort(l1) << 16);
                __nv_bfloat16* r1p = base + (size_t)row1 * ldc + col;
                *(uint32_t*)(r1p)       = hp;
                *(uint32_t*)(r1p + oh2) = hp;
                *(uint32_t*)(r1p + olo) = lp;
            }
        }
    }
}

// ---------------- softmax + split(A-pattern) over rows of N_=2048 ----------------
__global__ void softmax_split_kernel(const float* __restrict__ S,
                                     __nv_bfloat16* __restrict__ Ssp)
{
    __shared__ float red[256];
    const size_t rowi = blockIdx.x;
    const float* row = S + rowi * N_;
    __nv_bfloat16* orow = Ssp + rowi * (size_t)(3 * N_);
    const int tid = threadIdx.x;

    float4 v0 = ((const float4*)row)[tid];
    float4 v1 = ((const float4*)row)[tid + 256];

    float m = fmaxf(fmaxf(fmaxf(v0.x, v0.y), fmaxf(v0.z, v0.w)),
                    fmaxf(fmaxf(v1.x, v1.y), fmaxf(v1.z, v1.w)));
    red[tid] = m;
    __syncthreads();
    for (int s = 128; s > 0; s >>= 1) {
        if (tid < s) red[tid] = fmaxf(red[tid], red[tid + s]);
        __syncthreads();
    }
    const float rowmax = red[0];
    __syncthreads();

    v0.x = expf(v0.x - rowmax); v0.y = expf(v0.y - rowmax);
    v0.z = expf(v0.z - rowmax); v0.w = expf(v0.w - rowmax);
    v1.x = expf(v1.x - rowmax); v1.y = expf(v1.y - rowmax);
    v1.z = expf(v1.z - rowmax); v1.w = expf(v1.w - rowmax);

    float sum = (v0.x + v0.y + v0.z + v0.w) + (v1.x + v1.y + v1.z + v1.w);
    red[tid] = sum;
    __syncthreads();
    for (int s = 128; s > 0; s >>= 1) {
        if (tid < s) red[tid] += red[tid + s];
        __syncthreads();
    }
    const float inv = 1.0f / red[0];

    v0.x *= inv; v0.y *= inv; v0.z *= inv; v0.w *= inv;
    v1.x *= inv; v1.y *= inv; v1.z *= inv; v1.w *= inv;

    float vv[8] = {v0.x, v0.y, v0.z, v0.w, v1.x, v1.y, v1.z, v1.w};
    int pos[2] = {tid * 4, 1024 + tid * 4};
#pragma unroll
    for (int gsel = 0; gsel < 2; gsel++) {
        __nv_bfloat16 h[4], l[4];
#pragma unroll
        for (int q = 0; q < 4; q++) split2(vv[gsel * 4 + q], h[q], l[q]);
        uint32_t h01 = (uint32_t)__bfloat16_as_ushort(h[0]) | ((uint32_t)__bfloat16_as_ushort(h[1]) << 16);
        uint32_t h23 = (uint32_t)__bfloat16_as_ushort(h[2]) | ((uint32_t)__bfloat16_as_ushort(h[3]) << 16);
        uint32_t l01 = (uint32_t)__bfloat16_as_ushort(l[0]) | ((uint32_t)__bfloat16_as_ushort(l[1]) << 16);
        uint32_t l23 = (uint32_t)__bfloat16_as_ushort(l[2]) | ((uint32_t)__bfloat16_as_ushort(l[3]) << 16);
        int p = pos[gsel];
        *(uint2*)(orow + p)          = make_uint2(h01, h23);
        *(uint2*)(orow + N_ + p)     = make_uint2(h01, h23);
        *(uint2*)(orow + 2 * N_ + p) = make_uint2(l01, l23);
    }
}

// ---------------- BN batch statistics per channel ----------------
__global__ void bn_stats_kernel(const float* __restrict__ zp,
                                const float* __restrict__ gamma,
                                const float* __restrict__ beta,
                                float* __restrict__ scale,
                                float* __restrict__ shift)
{
    __shared__ double rs[256];
    __shared__ double rs2[256];
    const int c = blockIdx.x;
    const int tid = threadIdx.x;
    const float* row = zp + (size_t)c * (B_ * N_);

    double s = 0.0, s2 = 0.0;
    const int n4 = (B_ * N_) / 4;
    for (int i = tid; i < n4; i += 256) {
        float4 v = ((const float4*)row)[i];
        s  += (double)v.x + (double)v.y + (double)v.z + (double)v.w;
        s2 += (double)v.x * v.x + (double)v.y * v.y +
              (double)v.z * v.z + (double)v.w * v.w;
    }
    rs[tid] = s; rs2[tid] = s2;
    __syncthreads();
    for (int st = 128; st > 0; st >>= 1) {
        if (tid < st) { rs[tid] += rs[tid + st]; rs2[tid] += rs2[tid + st]; }
        __syncthreads();
    }
    if (tid == 0) {
        const double M = (double)(B_ * N_);
        double mean = rs[0] / M;
        double var  = rs2[0] / M - mean * mean;
        double inv  = 1.0 / sqrt(var + 1e-5);
        double sc   = (double)gamma[c] * inv;
        scale[c] = (float)sc;
        shift[c] = (float)((double)beta[c] - mean * sc);
    }
}

// ---------------- finalize ----------------
__global__ void finalize_kernel(const float* __restrict__ zp,
                                const float* __restrict__ x,
                                const float* __restrict__ scale,
                                const float* __restrict__ shift,
                                float* __restrict__ out)
{
    const size_t idx4 = (size_t)blockIdx.x * blockDim.x + threadIdx.x;
    const size_t total4 = (size_t)B_ * C_ * N_ / 4;
    if (idx4 >= total4) return;
    const int nq = N_ / 4;
    int n4 = (int)(idx4 % nq);
    int c  = (int)((idx4 / nq) % C_);
    int b  = (int)(idx4 / ((size_t)nq * C_));

    float4 z = ((const float4*)zp)[(size_t)c * (B_ * N_ / 4) + (size_t)b * nq + n4];
    float4 xv = ((const float4*)x)[idx4];
    const float sc = scale[c], sh = shift[c];
    float4 o;
    o.x = z.x * sc + sh + xv.x;
    o.y = z.y * sc + sh + xv.y;
    o.z = z.z * sc + sh + xv.z;
    o.w = z.w * sc + sh + xv.w;
    ((float4*)out)[idx4] = o;
}

// ---------------- launch ----------------
template <typename T>
static T* sym_addr(const void* sym)
{
    void* p = nullptr;
    cudaGetSymbolAddress(&p, sym);
    return (T*)p;
}

extern "C" void kernel_launch(void* const* d_in, const int* in_sizes, int n_in,
                              void* d_out, int out_size)
{
    const float* x     = (const float*)d_in[0];
    const float* Wg    = (const float*)d_in[1];
    const float* Wth   = (const float*)d_in[2];
    const float* Wph   = (const float*)d_in[3];
    const float* Wz    = (const float*)d_in[4];
    const float* gamma = (const float*)d_in[5];
    const float* beta  = (const float*)d_in[6];
    float* out = (float*)d_out;

    __nv_bfloat16* xsA  = sym_addr<__nv_bfloat16>(d_xsA);
    __nv_bfloat16* xsB  = sym_addr<__nv_bfloat16>(d_xsB);
    __nv_bfloat16* WthS = sym_addr<__nv_bfloat16>(d_WthS);
    __nv_bfloat16* WphS = sym_addr<__nv_bfloat16>(d_WphS);
    __nv_bfloat16* WgS  = sym_addr<__nv_bfloat16>(d_WgS);
    __nv_bfloat16* WzS  = sym_addr<__nv_bfloat16>(d_WzS);
    __nv_bfloat16* thS  = sym_addr<__nv_bfloat16>(d_thS);
    __nv_bfloat16* phS  = sym_addr<__nv_bfloat16>(d_phS);
    __nv_bfloat16* gS   = sym_addr<__nv_bfloat16>(d_gS);
    float*         Sf   = sym_addr<float>(d_Sf);
    __nv_bfloat16* SsP  = sym_addr<__nv_bfloat16>(d_SsP);
    __nv_bfloat16* OS   = sym_addr<__nv_bfloat16>(d_OS);
    float* zp    = sym_addr<float>(d_zp);
    float* scale = sym_addr<float>(d_scale);
    float* shift = sym_addr<float>(d_shift);

    cudaFuncSetAttribute(gemm_mma_kernel,
                         cudaFuncAttributeMaxDynamicSharedMemorySize, GEMM_SMEM);

    // 1) weight splits
    split_all_kernel<<<dim3((P_ * C_ + 255) / 256, 4), 256>>>(
        Wth, Wph, Wg, Wz, WthS, WphS, WgS, WzS);
    // 2) x transpose + split
    xsplit_kernel<<<dim3(N_ / 32, C_ / 32, B_), dim3(32, 32)>>>(x, xsA, xsB);

    // 3) theta
    gemm_mma_kernel<<<dim3(P_ / 128, N_ / 128, B_), 256, GEMM_SMEM>>>(
        xsA, 3 * C_, WthS, 3 * C_, thS, 3 * P_, 3 * C_, 1, P_,
        (size_t)N_ * 3 * C_, 0, (size_t)N_ * 3 * P_);
    // 4) phi
    gemm_mma_kernel<<<dim3(P_ / 128, N_ / 128, B_), 256, GEMM_SMEM>>>(
        xsA, 3 * C_, WphS, 3 * C_, phS, 3 * P_, 3 * C_, 2, P_,
        (size_t)N_ * 3 * C_, 0, (size_t)N_ * 3 * P_);
    // 5) g^T
    gemm_mma_kernel<<<dim3(N_ / 128, P_ / 128, B_), 256, GEMM_SMEM>>>(
        WgS, 3 * C_, xsB, 3 * C_, gS, 3 * N_, 3 * C_, 2, N_,
        0, (size_t)N_ * 3 * C_, (size_t)P_ * 3 * N_);
    // 6) scores
    gemm_mma_kernel<<<dim3(N_ / 128, N_ / 128, B_), 256, GEMM_SMEM>>>(
        thS, 3 * P_, phS, 3 * P_, Sf, N_, 3 * P_, 0, 0,
        (size_t)N_ * 3 * P_, (size_t)N_ * 3 * P_, (size_t)N_ * N_);
    // 7) softmax + split
    softmax_split_kernel<<<B_ * N_, 256>>>(Sf, SsP);
    // 8) PV
    gemm_mma_kernel<<<dim3(P_ / 128, N_ / 128, B_), 256, GEMM_SMEM>>>(
        SsP, 3 * N_, gS, 3 * N_, OS, 3 * P_, 3 * N_, 2, P_,
        (size_t)N_ * 3 * N_, (size_t)P_ * 3 * N_, (size_t)N_ * 3 * P_);
    // 9) z
    gemm_mma_kernel<<<dim3((B_ * N_) / 128, C_ / 128, 1), 256, GEMM_SMEM>>>(
        WzS, 3 * P_, OS, 3 * P_, zp, B_ * N_, 3 * P_, 0, 0, 0, 0, 0);

    // 10) BN + finalize
    bn_stats_kernel<<<C_, 256>>>(zp, gamma, beta, scale, shift);
    {
        const int total4 = B_ * C_ * N_ / 4;
        finalize_kernel<<<(total4 + 255) / 256, 256>>>(zp, x, scale, shift, out);
    }
}